// round 13
// baseline (speedup 1.0000x reference)
#include <cuda_runtime.h>
#include <cuda_bf16.h>
#include <cstdint>

#define S_LEN 4096
#define H_DIM 1024
#define NHEAD 16
#define HD    64
#define KSEL  32
#define KA    2048           // A split: [hi | lo]
#define KB    3072           // B split: [hi | hi | lo]

// ---------------------------------------------------------------------------
// Scratch (allocation-free device globals)
// ---------------------------------------------------------------------------
__device__ float g_Q[S_LEN * H_DIM];
__device__ float g_K[S_LEN * H_DIM];
__device__ float g_V[S_LEN * H_DIM];
__device__ float g_O[S_LEN * H_DIM];

__device__ __nv_bfloat16 g_Ax[S_LEN * KA];      // split(x):  [hi, lo]
__device__ __nv_bfloat16 g_Ao[S_LEN * KA];      // split(O)
__device__ __nv_bfloat16 g_Wq2[H_DIM * KB];     // split(W^T): [hi, hi, lo]
__device__ __nv_bfloat16 g_Wk2[H_DIM * KB];
__device__ __nv_bfloat16 g_Wv2[H_DIM * KB];
__device__ __nv_bfloat16 g_Wo2[H_DIM * KB];

// ---------------------------------------------------------------------------
// Baseline-PTX helpers (valid on plain sm_103 target)
// ---------------------------------------------------------------------------
__device__ __forceinline__ uint32_t smem_u32(const void* p) {
    uint32_t a;
    asm("{ .reg .u64 t; cvta.to.shared.u64 t, %1; cvt.u32.u64 %0, t; }"
        : "=r"(a) : "l"(p));
    return a;
}
__device__ __forceinline__ void cp_async16(uint32_t saddr, const void* g) {
    asm volatile("cp.async.cg.shared.global [%0], [%1], 16;"
                 :: "r"(saddr), "l"(g) : "memory");
}
#define CP_COMMIT() asm volatile("cp.async.commit_group;" ::: "memory")
#define CP_WAIT1()  asm volatile("cp.async.wait_group 1;" ::: "memory")
#define CP_WAIT0()  asm volatile("cp.async.wait_group 0;" ::: "memory")

__device__ __forceinline__ void ldsm_x4(uint32_t& r0, uint32_t& r1,
                                        uint32_t& r2, uint32_t& r3,
                                        uint32_t addr) {
    asm volatile("ldmatrix.sync.aligned.m8n8.x4.shared.b16 {%0,%1,%2,%3}, [%4];"
                 : "=r"(r0), "=r"(r1), "=r"(r2), "=r"(r3) : "r"(addr));
}
__device__ __forceinline__ void mma_bf16(float* d, const uint32_t* a,
                                         uint32_t b0, uint32_t b1) {
    asm volatile(
        "mma.sync.aligned.m16n8k16.row.col.f32.bf16.bf16.f32 "
        "{%0,%1,%2,%3}, {%4,%5,%6,%7}, {%8,%9}, {%0,%1,%2,%3};"
        : "+f"(d[0]), "+f"(d[1]), "+f"(d[2]), "+f"(d[3])
        : "r"(a[0]), "r"(a[1]), "r"(a[2]), "r"(a[3]), "r"(b0), "r"(b1));
}

// ---------------------------------------------------------------------------
// HMMA GEMM core: C[4096,1024] += A'[4096, hi|lo] x B'[1024, hi|hi|lo]^T
// CTA 128x128, 8 warps (2x4), warp tile 64x32, KC=32, 3-stage cp.async.
// A k-chunks 64..95 remap to A's hi half (0..31).
// ---------------------------------------------------------------------------
#define KC 32
#define NCHUNK (KB / KC)            // 96
#define NCH_A  (KA / KC)            // 64
#define TSTRIDE 80                  // bytes per 32-bf16 smem row (conflict-free)
#define TILE_B (128 * TSTRIDE)      // 10240 per operand tile
#define STAGE_B (2 * TILE_B)        // A+B per stage
#define GEMM_SMEM (3 * STAGE_B)     // 61440 B (dynamic)

template <bool HAS_BIAS>
__device__ __forceinline__
void gemm_body(const __nv_bfloat16* __restrict__ A,
               const __nv_bfloat16* __restrict__ B,
               float* __restrict__ C,
               const float* __restrict__ bias,
               char* smem)
{
    const int tid  = threadIdx.x;
    const int wid  = tid >> 5;
    const int lane = tid & 31;
    const int warpM = (wid >> 2) * 64;
    const int warpN = (wid & 3) * 32;
    const int blockCol = blockIdx.x * 128;
    const int blockRow = blockIdx.y * 128;

    const uint32_t sbase = smem_u32(smem);
    const char* Ag = (const char*)(A + (size_t)blockRow * KA);
    const char* Bg = (const char*)(B + (size_t)blockCol * KB);
    const size_t rowA = (size_t)KA * 2;   // 4096
    const size_t rowB = (size_t)KB * 2;   // 6144

    const int lrow0 = tid >> 2, lseg = (tid & 3) * 16;
    const int lrow1 = lrow0 + 64;

    float acc[4][4][4];
#pragma unroll
    for (int i = 0; i < 4; ++i)
#pragma unroll
        for (int j = 0; j < 4; ++j)
#pragma unroll
            for (int r = 0; r < 4; ++r) acc[i][j][r] = 0.0f;

    const int a_row = (lane & 15);
    const int a_kb  = (lane >> 4) * 16;
    const int b_row = (lane & 7);
    const int b_kb  = (lane >> 3) * 16;

    auto issue = [&](int c) {
        const uint32_t sA = sbase + (uint32_t)(c % 3) * STAGE_B;
        const uint32_t sB = sA + TILE_B;
        const int ca = (c < NCH_A) ? c : (c - NCH_A);   // A hi-half remap
        const size_t koa = (size_t)ca * 64;
        const size_t kob = (size_t)c * 64;
        cp_async16(sA + lrow0 * TSTRIDE + lseg, Ag + lrow0 * rowA + koa + lseg);
        cp_async16(sA + lrow1 * TSTRIDE + lseg, Ag + lrow1 * rowA + koa + lseg);
        cp_async16(sB + lrow0 * TSTRIDE + lseg, Bg + lrow0 * rowB + kob + lseg);
        cp_async16(sB + lrow1 * TSTRIDE + lseg, Bg + lrow1 * rowB + kob + lseg);
        CP_COMMIT();
    };

    issue(0);
    issue(1);

    for (int c = 0; c < NCHUNK; ++c) {
        CP_WAIT1();            // stage c landed; c+1 may be in flight
        __syncthreads();
        if (c + 2 < NCHUNK) issue(c + 2);   // overwrites stage (c-1): all reads done

        const uint32_t sA = sbase + (uint32_t)(c % 3) * STAGE_B;
        const uint32_t sB = sA + TILE_B;

        uint32_t af[4][2][4];
        uint32_t bf[4][4];
#pragma unroll
        for (int mt = 0; mt < 4; ++mt) {
            const uint32_t base = sA + (warpM + mt * 16 + a_row) * TSTRIDE + a_kb;
            ldsm_x4(af[mt][0][0], af[mt][0][1], af[mt][0][2], af[mt][0][3], base);
            ldsm_x4(af[mt][1][0], af[mt][1][1], af[mt][1][2], af[mt][1][3], base + 32);
        }
#pragma unroll
        for (int nt = 0; nt < 4; ++nt) {
            const uint32_t base = sB + (warpN + nt * 8 + b_row) * TSTRIDE + b_kb;
            ldsm_x4(bf[nt][0], bf[nt][1], bf[nt][2], bf[nt][3], base);
        }
#pragma unroll
        for (int kst = 0; kst < 2; ++kst)
#pragma unroll
            for (int mt = 0; mt < 4; ++mt)
#pragma unroll
                for (int nt = 0; nt < 4; ++nt)
                    mma_bf16(acc[mt][nt], af[mt][kst],
                             bf[nt][kst * 2 + 0], bf[nt][kst * 2 + 1]);
    }

    const int erow = lane >> 2;
    const int ecol = (lane & 3) * 2;
#pragma unroll
    for (int mt = 0; mt < 4; ++mt) {
        const int row0 = blockRow + warpM + mt * 16 + erow;
#pragma unroll
        for (int nt = 0; nt < 4; ++nt) {
            const int col = blockCol + warpN + nt * 8 + ecol;
            float2 v0 = make_float2(acc[mt][nt][0], acc[mt][nt][1]);
            float2 v1 = make_float2(acc[mt][nt][2], acc[mt][nt][3]);
            if (HAS_BIAS) {
                const float2 bb = *(const float2*)(bias + col);
                v0.x += bb.x; v0.y += bb.y;
                v1.x += bb.x; v1.y += bb.y;
            }
            *(float2*)(C + (size_t)row0 * H_DIM + col) = v0;
            *(float2*)(C + (size_t)(row0 + 8) * H_DIM + col) = v1;
        }
    }
}

// Merged Q/K/V projection: grid.z selects weight/output; shares A in L2,
// packs 768 CTAs into one launch (kills 3x wave-quantization tails).
__global__ __launch_bounds__(256, 1)
void gemm_qkv(const __nv_bfloat16* __restrict__ A,
              const __nv_bfloat16* __restrict__ B0,
              const __nv_bfloat16* __restrict__ B1,
              const __nv_bfloat16* __restrict__ B2,
              float* __restrict__ C0,
              float* __restrict__ C1,
              float* __restrict__ C2)
{
    extern __shared__ __align__(16) char smem[];
    const __nv_bfloat16* B = (blockIdx.z == 0) ? B0 : (blockIdx.z == 1) ? B1 : B2;
    float* C = (blockIdx.z == 0) ? C0 : (blockIdx.z == 1) ? C1 : C2;
    gemm_body<false>(A, B, C, nullptr, smem);
}

__global__ __launch_bounds__(256, 1)
void gemm_out(const __nv_bfloat16* __restrict__ A,
              const __nv_bfloat16* __restrict__ B,
              float* __restrict__ C,
              const float* __restrict__ bias)
{
    extern __shared__ __align__(16) char smem[];
    gemm_body<true>(A, B, C, bias, smem);
}

// ---------------------------------------------------------------------------
// fp32 -> split-bf16 activations: out[m] = [hi(0:1024) | lo(1024:2048)]
// ---------------------------------------------------------------------------
__global__ __launch_bounds__(256)
void conv_split(const float* __restrict__ in, __nv_bfloat16* __restrict__ out)
{
    const int i = blockIdx.x * 256 + threadIdx.x;     // 4096*1024/4 float4
    const float4 v = ((const float4*)in)[i];
    const int m = i >> 8;
    const int k = (i & 255) * 4;

    __nv_bfloat16 h0 = __float2bfloat16(v.x), h1 = __float2bfloat16(v.y);
    __nv_bfloat16 h2 = __float2bfloat16(v.z), h3 = __float2bfloat16(v.w);
    __nv_bfloat16 l0 = __float2bfloat16(v.x - __bfloat162float(h0));
    __nv_bfloat16 l1 = __float2bfloat16(v.y - __bfloat162float(h1));
    __nv_bfloat16 l2 = __float2bfloat16(v.z - __bfloat162float(h2));
    __nv_bfloat16 l3 = __float2bfloat16(v.w - __bfloat162float(h3));

    __nv_bfloat16* base = out + (size_t)m * KA + k;
    __nv_bfloat162* ph = (__nv_bfloat162*)base;
    __nv_bfloat162* pl = (__nv_bfloat162*)(base + 1024);
    ph[0] = __halves2bfloat162(h0, h1);
    ph[1] = __halves2bfloat162(h2, h3);
    pl[0] = __halves2bfloat162(l0, l1);
    pl[1] = __halves2bfloat162(l2, l3);
}

// ---------------------------------------------------------------------------
// Weight transpose + split: out[n][k'] = [hi(W[:,n]) | hi | lo]
// ---------------------------------------------------------------------------
__global__ __launch_bounds__(256)
void conv_w(const float* __restrict__ W, __nv_bfloat16* __restrict__ out)
{
    __shared__ float t[32][33];
    const int k0 = blockIdx.x * 32, n0 = blockIdx.y * 32;
    const int tx = threadIdx.x, ty = threadIdx.y;   // (32, 8)
#pragma unroll
    for (int i = 0; i < 4; ++i)
        t[ty + 8 * i][tx] = W[(size_t)(k0 + ty + 8 * i) * H_DIM + n0 + tx];
    __syncthreads();
#pragma unroll
    for (int i = 0; i < 4; ++i) {
        const int n = n0 + ty + 8 * i;
        const float v = t[tx][ty + 8 * i];
        const __nv_bfloat16 h = __float2bfloat16(v);
        const __nv_bfloat16 l = __float2bfloat16(v - __bfloat162float(h));
        __nv_bfloat16* o = out + (size_t)n * KB + k0 + tx;
        o[0]    = h;
        o[1024] = h;
        o[2048] = l;
    }
}

// ---------------------------------------------------------------------------
// Gather-attention: one block per query, one warp per head.
// float2 gathers (1 LDG.64 per row) + 2-key ILP behind the shfl trees.
// ---------------------------------------------------------------------------
__global__ __launch_bounds__(512)
void attn_kernel(const int* __restrict__ idx,
                 const float* __restrict__ geo_bias)
{
    const int s = blockIdx.x;
    __shared__ int s_idx[KSEL];
    const int tid = threadIdx.x;
    if (tid < KSEL) s_idx[tid] = idx[s * KSEL + tid];
    __syncthreads();

    const int h = tid >> 5;
    const int lane = tid & 31;
    const unsigned FULL = 0xffffffffu;

    const float2 q = ((const float2*)(g_Q + (size_t)s * H_DIM + h * HD))[lane];

    float mylogit = 0.0f;
#pragma unroll 1
    for (int j = 0; j < KSEL; j += 2) {
        const int k0 = s_idx[j], k1 = s_idx[j + 1];
        const float2 a = ((const float2*)(g_K + (size_t)k0 * H_DIM + h * HD))[lane];
        const float2 b = ((const float2*)(g_K + (size_t)k1 * H_DIM + h * HD))[lane];
        float pa = q.x * a.x + q.y * a.y;
        float pb = q.x * b.x + q.y * b.y;
#pragma unroll
        for (int off = 16; off; off >>= 1) {
            pa += __shfl_xor_sync(FULL, pa, off);
            pb += __shfl_xor_sync(FULL, pb, off);
        }
        if (lane == j)     mylogit = pa;
        if (lane == j + 1) mylogit = pb;
    }

    const int myk = s_idx[lane];
    mylogit = mylogit * 0.125f
            + geo_bias[((size_t)h * S_LEN + s) * KSEL + lane];
    if (myk > s) mylogit = -1e30f;

    float m = mylogit;
#pragma unroll
    for (int off = 16; off; off >>= 1)
        m = fmaxf(m, __shfl_xor_sync(FULL, m, off));
    float e = __expf(mylogit - m);
    float sum = e;
#pragma unroll
    for (int off = 16; off; off >>= 1)
        sum += __shfl_xor_sync(FULL, sum, off);
    const float p = e / sum;

    float2 acc = make_float2(0.0f, 0.0f);
#pragma unroll 1
    for (int j = 0; j < KSEL; j += 2) {
        const float pj0 = __shfl_sync(FULL, p, j);
        const float pj1 = __shfl_sync(FULL, p, j + 1);
        const float2 v0 = ((const float2*)(g_V + (size_t)s_idx[j]     * H_DIM + h * HD))[lane];
        const float2 v1 = ((const float2*)(g_V + (size_t)s_idx[j + 1] * H_DIM + h * HD))[lane];
        acc.x = fmaf(pj0, v0.x, acc.x);
        acc.y = fmaf(pj0, v0.y, acc.y);
        acc.x = fmaf(pj1, v1.x, acc.x);
        acc.y = fmaf(pj1, v1.y, acc.y);
    }

    ((float2*)(g_O + (size_t)s * H_DIM + h * HD))[lane] = acc;
}

// ---------------------------------------------------------------------------
// Launch. Inputs (metadata order): x, idx, valid, geo_bias, Wq, Wk, Wv, Wo, bo
// ---------------------------------------------------------------------------
extern "C" void kernel_launch(void* const* d_in, const int* in_sizes, int n_in,
                              void* d_out, int out_size)
{
    const float* x   = (const float*)d_in[0];
    const int*   idx = (const int*)  d_in[1];
    const float* geo = (const float*)d_in[3];
    const float* Wq  = (const float*)d_in[4];
    const float* Wk  = (const float*)d_in[5];
    const float* Wv  = (const float*)d_in[6];
    const float* Wo  = (const float*)d_in[7];
    const float* bo  = (const float*)d_in[8];
    float* out = (float*)d_out;

    float *Q, *K, *V, *O;
    __nv_bfloat16 *Ax, *Ao, *Wq2, *Wk2, *Wv2, *Wo2;
    cudaGetSymbolAddress((void**)&Q,  g_Q);
    cudaGetSymbolAddress((void**)&K,  g_K);
    cudaGetSymbolAddress((void**)&V,  g_V);
    cudaGetSymbolAddress((void**)&O,  g_O);
    cudaGetSymbolAddress((void**)&Ax, g_Ax);
    cudaGetSymbolAddress((void**)&Ao, g_Ao);
    cudaGetSymbolAddress((void**)&Wq2, g_Wq2);
    cudaGetSymbolAddress((void**)&Wk2, g_Wk2);
    cudaGetSymbolAddress((void**)&Wv2, g_Wv2);
    cudaGetSymbolAddress((void**)&Wo2, g_Wo2);

    cudaFuncSetAttribute(gemm_qkv,
        cudaFuncAttributeMaxDynamicSharedMemorySize, GEMM_SMEM);
    cudaFuncSetAttribute(gemm_out,
        cudaFuncAttributeMaxDynamicSharedMemorySize, GEMM_SMEM);

    const dim3 wgrid(H_DIM / 32, H_DIM / 32);
    const dim3 wblk(32, 8);
    conv_split<<<S_LEN * H_DIM / 4 / 256, 256>>>(x, Ax);
    conv_w<<<wgrid, wblk>>>(Wq, Wq2);
    conv_w<<<wgrid, wblk>>>(Wk, Wk2);
    conv_w<<<wgrid, wblk>>>(Wv, Wv2);
    conv_w<<<wgrid, wblk>>>(Wo, Wo2);

    const dim3 qgrid(H_DIM / 128, S_LEN / 128, 3);   // (8, 32, 3)
    gemm_qkv<<<qgrid, 256, GEMM_SMEM>>>(Ax, Wq2, Wk2, Wv2, Q, K, V);

    attn_kernel<<<S_LEN, 512>>>(idx, geo);

    conv_split<<<S_LEN * H_DIM / 4 / 256, 256>>>(O, Ao);
    const dim3 ogrid(H_DIM / 128, S_LEN / 128);
    gemm_out<<<ogrid, 256, GEMM_SMEM>>>(Ao, Wo2, out, bo);
}

// round 17
// speedup vs baseline: 1.1641x; 1.1641x over previous
#include <cuda_runtime.h>
#include <cuda_bf16.h>
#include <cstdint>

#define S_LEN 4096
#define H_DIM 1024
#define NHEAD 16
#define HD    64
#define KSEL  32
#define KA    2048           // A split: [hi | lo]
#define KB    3072           // B split: [hi | hi | lo]

// ---------------------------------------------------------------------------
// Scratch (allocation-free device globals)
// ---------------------------------------------------------------------------
__device__ float g_Q[S_LEN * H_DIM];
__device__ float g_K[S_LEN * H_DIM];
__device__ float g_V[S_LEN * H_DIM];
__device__ float g_O[S_LEN * H_DIM];

__device__ __nv_bfloat16 g_Ax[S_LEN * KA];      // split(x):  [hi, lo]
__device__ __nv_bfloat16 g_Ao[S_LEN * KA];      // split(O)
__device__ __nv_bfloat16 g_Wq2[H_DIM * KB];     // split(W^T): [hi, hi, lo]
__device__ __nv_bfloat16 g_Wk2[H_DIM * KB];
__device__ __nv_bfloat16 g_Wv2[H_DIM * KB];
__device__ __nv_bfloat16 g_Wo2[H_DIM * KB];

// ---------------------------------------------------------------------------
// Baseline-PTX helpers (valid on plain sm_103 target)
// ---------------------------------------------------------------------------
__device__ __forceinline__ uint32_t smem_u32(const void* p) {
    uint32_t a;
    asm("{ .reg .u64 t; cvta.to.shared.u64 t, %1; cvt.u32.u64 %0, t; }"
        : "=r"(a) : "l"(p));
    return a;
}
__device__ __forceinline__ void cp_async16(uint32_t saddr, const void* g) {
    asm volatile("cp.async.cg.shared.global [%0], [%1], 16;"
                 :: "r"(saddr), "l"(g) : "memory");
}
#define CP_COMMIT() asm volatile("cp.async.commit_group;" ::: "memory")
#define CP_WAIT0()  asm volatile("cp.async.wait_group 0;" ::: "memory")

__device__ __forceinline__ void ldsm_x4(uint32_t& r0, uint32_t& r1,
                                        uint32_t& r2, uint32_t& r3,
                                        uint32_t addr) {
    asm volatile("ldmatrix.sync.aligned.m8n8.x4.shared.b16 {%0,%1,%2,%3}, [%4];"
                 : "=r"(r0), "=r"(r1), "=r"(r2), "=r"(r3) : "r"(addr));
}
__device__ __forceinline__ void mma_bf16(float* d, const uint32_t* a,
                                         uint32_t b0, uint32_t b1) {
    asm volatile(
        "mma.sync.aligned.m16n8k16.row.col.f32.bf16.bf16.f32 "
        "{%0,%1,%2,%3}, {%4,%5,%6,%7}, {%8,%9}, {%0,%1,%2,%3};"
        : "+f"(d[0]), "+f"(d[1]), "+f"(d[2]), "+f"(d[3])
        : "r"(a[0]), "r"(a[1]), "r"(a[2]), "r"(a[3]), "r"(b0), "r"(b1));
}

// ---------------------------------------------------------------------------
// HMMA GEMM (R8 structure, known-good):
//   C[4096,1024] = A'[4096, hi|lo] x B'[1024, hi|hi|lo]^T
// CTA 128x128, 8 warps (2x4), warp tile 64x32, KC=32, 2-stage cp.async with
// the copy-wait placed AFTER the MMA block (overlaps copy with math).
// A k-chunks 64..95 remap to A's hi half (0..31).
// ---------------------------------------------------------------------------
#define KC 32
#define NCHUNK (KB / KC)            // 96
#define NCH_A  (KA / KC)            // 64
#define TSTRIDE 80                  // bytes per 32-bf16 smem row (conflict-free)
#define TILE_B (128 * TSTRIDE)      // 10240 per operand tile

template <bool HAS_BIAS>
__global__ __launch_bounds__(256, 1)
void gemm_mma(const __nv_bfloat16* __restrict__ A,
              const __nv_bfloat16* __restrict__ B,
              float* __restrict__ C,
              const float* __restrict__ bias)
{
    __shared__ __align__(16) char smem[4 * TILE_B];   // A0 B0 A1 B1

    const int tid  = threadIdx.x;
    const int wid  = tid >> 5;
    const int lane = tid & 31;
    const int warpM = (wid >> 2) * 64;   // 0 or 64
    const int warpN = (wid & 3) * 32;    // 0..96
    const int blockCol = blockIdx.x * 128;
    const int blockRow = blockIdx.y * 128;

    const uint32_t sbase = smem_u32(smem);
    const char* Ag = (const char*)(A + (size_t)blockRow * KA);
    const char* Bg = (const char*)(B + (size_t)blockCol * KB);
    const size_t rowA = (size_t)KA * 2;   // 4096
    const size_t rowB = (size_t)KB * 2;   // 6144

    // loader mapping: 512 uint4 per tile, 2 per thread per operand
    const int lrow0 = tid >> 2, lseg = (tid & 3) * 16;
    const int lrow1 = lrow0 + 64;

    float acc[4][4][4];
#pragma unroll
    for (int i = 0; i < 4; ++i)
#pragma unroll
        for (int j = 0; j < 4; ++j)
#pragma unroll
            for (int r = 0; r < 4; ++r) acc[i][j][r] = 0.0f;

    // ldmatrix lane addressing
    const int a_row = (lane & 15);
    const int a_kb  = (lane >> 4) * 16;      // 0 / 16
    const int b_row = (lane & 7);
    const int b_kb  = (lane >> 3) * 16;      // 0,16,32,48

    auto issue = [&](int c) {
        const int b = c & 1;
        const uint32_t sA = sbase + b * 2 * TILE_B;
        const uint32_t sB = sA + TILE_B;
        const int ca = (c < NCH_A) ? c : (c - NCH_A);   // A hi-half remap
        const size_t koa = (size_t)ca * 64;              // KC*2 bytes
        const size_t kob = (size_t)c * 64;
        cp_async16(sA + lrow0 * TSTRIDE + lseg, Ag + lrow0 * rowA + koa + lseg);
        cp_async16(sA + lrow1 * TSTRIDE + lseg, Ag + lrow1 * rowA + koa + lseg);
        cp_async16(sB + lrow0 * TSTRIDE + lseg, Bg + lrow0 * rowB + kob + lseg);
        cp_async16(sB + lrow1 * TSTRIDE + lseg, Bg + lrow1 * rowB + kob + lseg);
        CP_COMMIT();
    };

    issue(0);
    CP_WAIT0();
    __syncthreads();

    for (int c = 0; c < NCHUNK; ++c) {
        if (c + 1 < NCHUNK) issue(c + 1);

        const int b = c & 1;
        const uint32_t sA = sbase + b * 2 * TILE_B;
        const uint32_t sB = sA + TILE_B;

        uint32_t af[4][2][4];   // [mt][kst][reg]
        uint32_t bf[4][4];      // [nt][kst*2 + reg]
#pragma unroll
        for (int mt = 0; mt < 4; ++mt) {
            const uint32_t base = sA + (warpM + mt * 16 + a_row) * TSTRIDE + a_kb;
            ldsm_x4(af[mt][0][0], af[mt][0][1], af[mt][0][2], af[mt][0][3], base);
            ldsm_x4(af[mt][1][0], af[mt][1][1], af[mt][1][2], af[mt][1][3], base + 32);
        }
#pragma unroll
        for (int nt = 0; nt < 4; ++nt) {
            const uint32_t base = sB + (warpN + nt * 8 + b_row) * TSTRIDE + b_kb;
            ldsm_x4(bf[nt][0], bf[nt][1], bf[nt][2], bf[nt][3], base);
        }
#pragma unroll
        for (int kst = 0; kst < 2; ++kst)
#pragma unroll
            for (int mt = 0; mt < 4; ++mt)
#pragma unroll
                for (int nt = 0; nt < 4; ++nt)
                    mma_bf16(acc[mt][nt], af[mt][kst],
                             bf[nt][kst * 2 + 0], bf[nt][kst * 2 + 1]);

        if (c + 1 < NCHUNK) {
            CP_WAIT0();        // after MMA: copy latency overlapped with math
        }
        __syncthreads();
    }

    // Epilogue
    const int erow = lane >> 2;
    const int ecol = (lane & 3) * 2;
#pragma unroll
    for (int mt = 0; mt < 4; ++mt) {
        const int row0 = blockRow + warpM + mt * 16 + erow;
#pragma unroll
        for (int nt = 0; nt < 4; ++nt) {
            const int col = blockCol + warpN + nt * 8 + ecol;
            float2 v0 = make_float2(acc[mt][nt][0], acc[mt][nt][1]);
            float2 v1 = make_float2(acc[mt][nt][2], acc[mt][nt][3]);
            if (HAS_BIAS) {
                const float2 bb = *(const float2*)(bias + col);
                v0.x += bb.x; v0.y += bb.y;
                v1.x += bb.x; v1.y += bb.y;
            }
            *(float2*)(C + (size_t)row0 * H_DIM + col) = v0;
            *(float2*)(C + (size_t)(row0 + 8) * H_DIM + col) = v1;
        }
    }
}

// ---------------------------------------------------------------------------
// fp32 -> split-bf16 activations: out[m] = [hi(0:1024) | lo(1024:2048)]
// ---------------------------------------------------------------------------
__global__ __launch_bounds__(256)
void conv_split(const float* __restrict__ in, __nv_bfloat16* __restrict__ out)
{
    const int i = blockIdx.x * 256 + threadIdx.x;     // 4096*1024/4 float4
    const float4 v = ((const float4*)in)[i];
    const int m = i >> 8;
    const int k = (i & 255) * 4;

    __nv_bfloat16 h0 = __float2bfloat16(v.x), h1 = __float2bfloat16(v.y);
    __nv_bfloat16 h2 = __float2bfloat16(v.z), h3 = __float2bfloat16(v.w);
    __nv_bfloat16 l0 = __float2bfloat16(v.x - __bfloat162float(h0));
    __nv_bfloat16 l1 = __float2bfloat16(v.y - __bfloat162float(h1));
    __nv_bfloat16 l2 = __float2bfloat16(v.z - __bfloat162float(h2));
    __nv_bfloat16 l3 = __float2bfloat16(v.w - __bfloat162float(h3));

    __nv_bfloat16* base = out + (size_t)m * KA + k;
    __nv_bfloat162* ph = (__nv_bfloat162*)base;
    __nv_bfloat162* pl = (__nv_bfloat162*)(base + 1024);
    ph[0] = __halves2bfloat162(h0, h1);
    ph[1] = __halves2bfloat162(h2, h3);
    pl[0] = __halves2bfloat162(l0, l1);
    pl[1] = __halves2bfloat162(l2, l3);
}

// ---------------------------------------------------------------------------
// Weight transpose + split: out[n][k'] = [hi(W[:,n]) | hi | lo]
// ---------------------------------------------------------------------------
__global__ __launch_bounds__(256)
void conv_w(const float* __restrict__ W, __nv_bfloat16* __restrict__ out)
{
    __shared__ float t[32][33];
    const int k0 = blockIdx.x * 32, n0 = blockIdx.y * 32;
    const int tx = threadIdx.x, ty = threadIdx.y;   // (32, 8)
#pragma unroll
    for (int i = 0; i < 4; ++i)
        t[ty + 8 * i][tx] = W[(size_t)(k0 + ty + 8 * i) * H_DIM + n0 + tx];
    __syncthreads();
#pragma unroll
    for (int i = 0; i < 4; ++i) {
        const int n = n0 + ty + 8 * i;
        const float v = t[tx][ty + 8 * i];
        const __nv_bfloat16 h = __float2bfloat16(v);
        const __nv_bfloat16 l = __float2bfloat16(v - __bfloat162float(h));
        __nv_bfloat16* o = out + (size_t)n * KB + k0 + tx;
        o[0]    = h;
        o[1024] = h;
        o[2048] = l;
    }
}

// ---------------------------------------------------------------------------
// Gather-attention: one block per query, one warp per head.
// float2 gathers (1 LDG.64 per row) + 2-key ILP behind the shfl trees.
// ---------------------------------------------------------------------------
__global__ __launch_bounds__(512)
void attn_kernel(const int* __restrict__ idx,
                 const float* __restrict__ geo_bias)
{
    const int s = blockIdx.x;
    __shared__ int s_idx[KSEL];
    const int tid = threadIdx.x;
    if (tid < KSEL) s_idx[tid] = idx[s * KSEL + tid];
    __syncthreads();

    const int h = tid >> 5;
    const int lane = tid & 31;
    const unsigned FULL = 0xffffffffu;

    const float2 q = ((const float2*)(g_Q + (size_t)s * H_DIM + h * HD))[lane];

    float mylogit = 0.0f;
#pragma unroll 1
    for (int j = 0; j < KSEL; j += 2) {
        const int k0 = s_idx[j], k1 = s_idx[j + 1];
        const float2 a = ((const float2*)(g_K + (size_t)k0 * H_DIM + h * HD))[lane];
        const float2 b = ((const float2*)(g_K + (size_t)k1 * H_DIM + h * HD))[lane];
        float pa = q.x * a.x + q.y * a.y;
        float pb = q.x * b.x + q.y * b.y;
#pragma unroll
        for (int off = 16; off; off >>= 1) {
            pa += __shfl_xor_sync(FULL, pa, off);
            pb += __shfl_xor_sync(FULL, pb, off);
        }
        if (lane == j)     mylogit = pa;
        if (lane == j + 1) mylogit = pb;
    }

    const int myk = s_idx[lane];
    mylogit = mylogit * 0.125f
            + geo_bias[((size_t)h * S_LEN + s) * KSEL + lane];
    if (myk > s) mylogit = -1e30f;

    float m = mylogit;
#pragma unroll
    for (int off = 16; off; off >>= 1)
        m = fmaxf(m, __shfl_xor_sync(FULL, m, off));
    float e = __expf(mylogit - m);
    float sum = e;
#pragma unroll
    for (int off = 16; off; off >>= 1)
        sum += __shfl_xor_sync(FULL, sum, off);
    const float p = e / sum;

    float2 acc = make_float2(0.0f, 0.0f);
#pragma unroll 1
    for (int j = 0; j < KSEL; j += 2) {
        const float pj0 = __shfl_sync(FULL, p, j);
        const float pj1 = __shfl_sync(FULL, p, j + 1);
        const float2 v0 = ((const float2*)(g_V + (size_t)s_idx[j]     * H_DIM + h * HD))[lane];
        const float2 v1 = ((const float2*)(g_V + (size_t)s_idx[j + 1] * H_DIM + h * HD))[lane];
        acc.x = fmaf(pj0, v0.x, acc.x);
        acc.y = fmaf(pj0, v0.y, acc.y);
        acc.x = fmaf(pj1, v1.x, acc.x);
        acc.y = fmaf(pj1, v1.y, acc.y);
    }

    ((float2*)(g_O + (size_t)s * H_DIM + h * HD))[lane] = acc;
}

// ---------------------------------------------------------------------------
// Launch. Inputs (metadata order): x, idx, valid, geo_bias, Wq, Wk, Wv, Wo, bo
// ---------------------------------------------------------------------------
extern "C" void kernel_launch(void* const* d_in, const int* in_sizes, int n_in,
                              void* d_out, int out_size)
{
    const float* x   = (const float*)d_in[0];
    const int*   idx = (const int*)  d_in[1];
    const float* geo = (const float*)d_in[3];
    const float* Wq  = (const float*)d_in[4];
    const float* Wk  = (const float*)d_in[5];
    const float* Wv  = (const float*)d_in[6];
    const float* Wo  = (const float*)d_in[7];
    const float* bo  = (const float*)d_in[8];
    float* out = (float*)d_out;

    float *Q, *K, *V, *O;
    __nv_bfloat16 *Ax, *Ao, *Wq2, *Wk2, *Wv2, *Wo2;
    cudaGetSymbolAddress((void**)&Q,  g_Q);
    cudaGetSymbolAddress((void**)&K,  g_K);
    cudaGetSymbolAddress((void**)&V,  g_V);
    cudaGetSymbolAddress((void**)&O,  g_O);
    cudaGetSymbolAddress((void**)&Ax, g_Ax);
    cudaGetSymbolAddress((void**)&Ao, g_Ao);
    cudaGetSymbolAddress((void**)&Wq2, g_Wq2);
    cudaGetSymbolAddress((void**)&Wk2, g_Wk2);
    cudaGetSymbolAddress((void**)&Wv2, g_Wv2);
    cudaGetSymbolAddress((void**)&Wo2, g_Wo2);

    const dim3 wgrid(H_DIM / 32, H_DIM / 32);
    const dim3 wblk(32, 8);
    conv_split<<<S_LEN * H_DIM / 4 / 256, 256>>>(x, Ax);
    conv_w<<<wgrid, wblk>>>(Wq, Wq2);
    conv_w<<<wgrid, wblk>>>(Wk, Wk2);
    conv_w<<<wgrid, wblk>>>(Wv, Wv2);
    conv_w<<<wgrid, wblk>>>(Wo, Wo2);

    const dim3 ggrid(H_DIM / 128, S_LEN / 128);   // (8, 32)
    gemm_mma<false><<<ggrid, 256>>>(Ax, Wq2, Q, nullptr);
    gemm_mma<false><<<ggrid, 256>>>(Ax, Wk2, K, nullptr);
    gemm_mma<false><<<ggrid, 256>>>(Ax, Wv2, V, nullptr);

    attn_kernel<<<S_LEN, 512>>>(idx, geo);

    conv_split<<<S_LEN * H_DIM / 4 / 256, 256>>>(O, Ao);
    const dim3 ogrid(H_DIM / 128, S_LEN / 128);
    gemm_mma<true><<<ogrid, 256>>>(Ao, Wo2, out, bo);
}